// round 10
// baseline (speedup 1.0000x reference)
#include <cuda_runtime.h>
#include <cuda_fp16.h>
#include <cstdint>
#include <mma.h>

using namespace nvcuda;

// ---------------------------------------------------------------------------
// Problem constants
// ---------------------------------------------------------------------------
#define B_SZ   32
#define C_SZ   256      // C_in == C_out
#define PIX    4096     // 64*64
#define PODS   2

// scratch:  F = 2D-WHT(x) as fp16, transposed pixel order [b][c][w*64+h]
// scratch2: S = sum_p softthr(v*W@F) as fp16 (same pixel order)
__device__ __half  g_scratch [(size_t)B_SZ * C_SZ * PIX];   // 64 MiB
__device__ __half  g_scratch2[(size_t)B_SZ * C_SZ * PIX];   // 64 MiB
__device__ __half  g_Wh[(size_t)PODS * C_SZ * C_SZ];        // W in fp16
__device__ float4  g_vt[PIX];   // per scratch-pixel: (v0, T0, v1, T1)

// ---------------------------------------------------------------------------
// cp.async helpers (portable sm_80+)
// ---------------------------------------------------------------------------
__device__ __forceinline__ void cp_async16(void* smem_dst, const void* gsrc) {
    unsigned int s = (unsigned int)__cvta_generic_to_shared(smem_dst);
    asm volatile("cp.async.cg.shared.global [%0], [%1], 16;\n" :: "r"(s), "l"(gsrc));
}
#define CP_COMMIT() asm volatile("cp.async.commit_group;\n" ::: "memory")
#define CP_WAIT0()  asm volatile("cp.async.wait_group 0;\n" ::: "memory")

// ---------------------------------------------------------------------------
// FWHT of 64 elements (a = elem[lane], b = elem[lane+32]) per warp.
// ---------------------------------------------------------------------------
__device__ __forceinline__ void fwht64(float& a, float& b, int lane) {
    float s = a + b;
    float d = a - b;
    a = s; b = d;
#pragma unroll
    for (int st = 16; st >= 1; st >>= 1) {
        float ta = __shfl_xor_sync(0xffffffffu, a, st);
        float tb = __shfl_xor_sync(0xffffffffu, b, st);
        a = (lane & st) ? (ta - a) : (a + ta);
        b = (lane & st) ? (tb - b) : (b + tb);
    }
}

// ---------------------------------------------------------------------------
// Kernel 0: prep — permuted (v,T) LUT + W -> fp16
// ---------------------------------------------------------------------------
__global__ void prep_kernel(const float* __restrict__ v, const float* __restrict__ T,
                            const float* __restrict__ W) {
    int i = blockIdx.x * 256 + threadIdx.x;
    if (i < PIX) {
        int p = i;                                    // scratch order: w*64+h
        int vidx = ((p & 63) << 6) | (p >> 6);        // natural order: h*64+w
        g_vt[p] = make_float4(v[vidx], T[vidx], v[PIX + vidx], T[PIX + vidx]);
    }
    for (int j = i; j < PODS * C_SZ * C_SZ; j += gridDim.x * 256)
        g_Wh[j] = __float2half_rn(W[j]);
}

// ---------------------------------------------------------------------------
// Kernel 1: forward 2D WHT per (b,c) image -> g_scratch fp16 ([w][h] order)
// ---------------------------------------------------------------------------
__global__ void __launch_bounds__(256) fwht_fwd_kernel(const float* __restrict__ x) {
    __shared__ float tile[64 * 65];
    const int img = blockIdx.x;                 // b*256 + c
    const float* src = x + (size_t)img * PIX;
    __half* dst = g_scratch + (size_t)img * PIX;
    const int t = threadIdx.x;
    const int warp = t >> 5, lane = t & 31;

    float a[8], b[8];
#pragma unroll
    for (int i = 0; i < 8; i++) {
        int r = warp * 8 + i;                  // r = h
        a[i] = src[r * 64 + lane];
        b[i] = src[r * 64 + lane + 32];
        fwht64(a[i], b[i], lane);
        tile[lane * 65 + r]        = a[i];
        tile[(lane + 32) * 65 + r] = b[i];
    }
    __syncthreads();
#pragma unroll
    for (int i = 0; i < 8; i++) {
        int w = warp * 8 + i;
        float aa = tile[w * 65 + lane];
        float bb = tile[w * 65 + lane + 32];
        fwht64(aa, bb, lane);
        dst[w * 64 + lane]      = __float2half_rn(aa);
        dst[w * 64 + lane + 32] = __float2half_rn(bb);
    }
}

// ---------------------------------------------------------------------------
// Kernel 2: fp16 wmma dual-pod GEMM + soft-threshold + pod-sum.
//   Grid: (64 pixtiles, 4 M-quarters, 32 b). CTA: M=64, N=64, K=256 in 8
//   chunks of 32, A double-buffered cp.async, B panel K-resident.
//   8 warps 2(M) x 4(N): warp tile 32x16 per pod, both pods.
//   3 CTAs/SM (smem 56KB, 85-reg cap via launch_bounds(256,3)).
// ---------------------------------------------------------------------------
#define NT     64
#define KCH    32
#define LDBH   72                               // halves; 144B rows
#define LDAH   40                               // halves;  80B rows
#define BS_HALVES    (256 * LDBH)               // 18432 halves = 36864 B
#define A_POD_HALVES (64 * LDAH)                // 2560 halves = 5120 B
#define GEMM_SMEM_BYTES ((BS_HALVES + 4 * A_POD_HALVES) * 2)   // 57344 B

__device__ __forceinline__ float softthr(float y, float vv, float tt) {
    float z = vv * y;
    return copysignf(fmaxf(fabsf(z) - tt, 0.0f), z);
}

__global__ void __launch_bounds__(256, 3) gemm_pods_kernel() {
    extern __shared__ __half smh[];
    __half* Bs   = smh;                          // [256][72]
    __half* Abuf = smh + BS_HALVES;              // 4 x 2560: [buf][pod]

    const int pix0 = blockIdx.x * NT;
    const int mq   = blockIdx.y;                 // M quarter (64 rows of o)
    const int b    = blockIdx.z;
    const int t    = threadIdx.x;
    const int warp = t >> 5, lane = t & 31;
    const int wm   = warp >> 2;                  // 0..1  (M, 32 rows)
    const int wn   = warp & 3;                   // 0..3  (N, 16 cols)

    const __half* Fb = g_scratch + (size_t)b * C_SZ * PIX;
    __half*       Ob = g_scratch2 + (size_t)b * C_SZ * PIX;
    const __half* W0 = g_Wh + (size_t)mq * 64 * C_SZ;
    const __half* W1 = W0 + (size_t)C_SZ * C_SZ;

    // ---- B panel: 256 (c) x 64 (pix) fp16, K-resident ----
#pragma unroll
    for (int i = 0; i < 8; i++) {
        int idx = i * 256 + t;                   // 2048 x 16B
        int r = idx >> 3, u = idx & 7;
        cp_async16(Bs + r * LDBH + u * 8, Fb + (size_t)r * PIX + pix0 + u * 8);
    }
    // ---- A chunk 0 (both pods): 64 rows x 32 halves each = 512 x 16B ----
    {
        int idx = t;                              // 2 iterations of 256
#pragma unroll
        for (int i = 0; i < 2; i++, idx += 256) {
            int pod = idx >> 8;
            int r = (idx & 255) >> 2, u = idx & 3;
            cp_async16(Abuf + pod * A_POD_HALVES + r * LDAH + u * 8,
                       (pod ? W1 : W0) + (size_t)r * C_SZ + u * 8);
        }
    }
    CP_COMMIT();

    wmma::fragment<wmma::accumulator, 16, 16, 16, float> acc0[2], acc1[2];
#pragma unroll
    for (int mi = 0; mi < 2; mi++) {
        wmma::fill_fragment(acc0[mi], 0.0f);
        wmma::fill_fragment(acc1[mi], 0.0f);
    }

#pragma unroll 1
    for (int kci = 0; kci < 8; kci++) {
        CP_WAIT0();
        __syncthreads();
        if (kci < 7) {
            int kc = (kci + 1) * KCH;
            __half* Ab = Abuf + ((kci + 1) & 1) * 2 * A_POD_HALVES;
            int idx = t;
#pragma unroll
            for (int i = 0; i < 2; i++, idx += 256) {
                int pod = idx >> 8;
                int r = (idx & 255) >> 2, u = idx & 3;
                cp_async16(Ab + pod * A_POD_HALVES + r * LDAH + u * 8,
                           (pod ? W1 : W0) + (size_t)r * C_SZ + kc + u * 8);
            }
            CP_COMMIT();
        }
        const __half* A0 = Abuf + (kci & 1) * 2 * A_POD_HALVES;
        const __half* A1 = A0 + A_POD_HALVES;
#pragma unroll
        for (int ks = 0; ks < KCH; ks += 16) {
            wmma::fragment<wmma::matrix_b, 16, 16, 16, __half, wmma::row_major> bf;
            wmma::load_matrix_sync(bf, Bs + (kci * KCH + ks) * LDBH + wn * 16, LDBH);
#pragma unroll
            for (int mi = 0; mi < 2; mi++) {
                wmma::fragment<wmma::matrix_a, 16, 16, 16, __half, wmma::row_major> af0, af1;
                wmma::load_matrix_sync(af0, A0 + (wm * 32 + mi * 16) * LDAH + ks, LDAH);
                wmma::load_matrix_sync(af1, A1 + (wm * 32 + mi * 16) * LDAH + ks, LDAH);
                wmma::mma_sync(acc0[mi], af0, bf, acc0[mi]);
                wmma::mma_sync(acc1[mi], af1, bf, acc1[mi]);
            }
        }
    }

    // ---- epilogue: warp-private fp32 patches (32x16 per pod) in dead smem ----
    __syncthreads();
    float* patch0 = reinterpret_cast<float*>(smh) + warp * 1792;
    float* patch1 = patch0 + 640;                // 32 rows x 20 stride

#pragma unroll
    for (int mi = 0; mi < 2; mi++) {
        wmma::store_matrix_sync(patch0 + mi * 16 * 20, acc0[mi], 20, wmma::mem_row_major);
        wmma::store_matrix_sync(patch1 + mi * 16 * 20, acc1[mi], 20, wmma::mem_row_major);
    }
    __syncwarp();

    {
        const int colbase = pix0 + wn * 16;
        const float4* vt = g_vt + colbase;
        const int r = lane;                           // 0..31 row within warp tile
        const int o = mq * 64 + wm * 32 + r;
        __half* dst = Ob + (size_t)o * PIX + colbase;
        unsigned int packed[8];
#pragma unroll
        for (int j2 = 0; j2 < 8; j2++) {
            float4 w4a = vt[j2 * 2 + 0];
            // interleave: handle two columns per packed half2
            float ya0 = patch0[r * 20 + j2 * 2 + 0];
            float yb0 = patch1[r * 20 + j2 * 2 + 0];
            float4 w4b = vt[j2 * 2 + 1];
            float ya1 = patch0[r * 20 + j2 * 2 + 1];
            float yb1 = patch1[r * 20 + j2 * 2 + 1];
            float s0 = softthr(ya0, w4a.x, w4a.y) + softthr(yb0, w4a.z, w4a.w);
            float s1 = softthr(ya1, w4b.x, w4b.y) + softthr(yb1, w4b.z, w4b.w);
            __half2 h2 = __floats2half2_rn(s0, s1);
            packed[j2] = *reinterpret_cast<unsigned int*>(&h2);
        }
        uint4* d4 = reinterpret_cast<uint4*>(dst);
        d4[0] = make_uint4(packed[0], packed[1], packed[2], packed[3]);
        d4[1] = make_uint4(packed[4], packed[5], packed[6], packed[7]);
    }
}

// ---------------------------------------------------------------------------
// Kernel 3: inverse 2D WHT (/4096) + residual; un-transposes scratch2 (fp16).
// ---------------------------------------------------------------------------
__global__ void __launch_bounds__(256) fwht_inv_kernel(const float* __restrict__ x,
                                                       float* __restrict__ out) {
    __shared__ float tile[64 * 65];
    const int img = blockIdx.x;
    const __half* src = g_scratch2 + (size_t)img * PIX; // [w][h] order
    const float* xr  = x + (size_t)img * PIX;           // [h][w] order
    float* dst = out + (size_t)img * PIX;               // [h][w] order
    const int t = threadIdx.x;
    const int warp = t >> 5, lane = t & 31;

    float a[8], b[8];
#pragma unroll
    for (int i = 0; i < 8; i++) {
        int w = warp * 8 + i;
        a[i] = __half2float(src[w * 64 + lane]);
        b[i] = __half2float(src[w * 64 + lane + 32]);
        fwht64(a[i], b[i], lane);
        tile[lane * 65 + w]        = a[i];
        tile[(lane + 32) * 65 + w] = b[i];
    }
    __syncthreads();

    const float inv = 1.0f / 4096.0f;
#pragma unroll
    for (int i = 0; i < 8; i++) {
        int h = warp * 8 + i;
        float aa = tile[h * 65 + lane];
        float bb = tile[h * 65 + lane + 32];
        fwht64(aa, bb, lane);
        dst[h * 64 + lane]      = aa * inv + xr[h * 64 + lane];
        dst[h * 64 + lane + 32] = bb * inv + xr[h * 64 + lane + 32];
    }
}

// ---------------------------------------------------------------------------
// Launch
// ---------------------------------------------------------------------------
extern "C" void kernel_launch(void* const* d_in, const int* in_sizes, int n_in,
                              void* d_out, int out_size) {
    const float* x  = (const float*)d_in[0];   // (32, 256, 64, 64)
    const float* v  = (const float*)d_in[1];   // (2, 64, 64)
    const float* W  = (const float*)d_in[2];   // (2, 256, 256)
    const float* T  = (const float*)d_in[3];   // (2, 64, 64)
    float* out = (float*)d_out;

    static bool attr_set = false;
    if (!attr_set) {
        cudaFuncSetAttribute(gemm_pods_kernel,
                             cudaFuncAttributeMaxDynamicSharedMemorySize,
                             GEMM_SMEM_BYTES);
        attr_set = true;
    }

    prep_kernel<<<PIX / 256, 256>>>(v, T, W);
    fwht_fwd_kernel<<<B_SZ * C_SZ, 256>>>(x);
    gemm_pods_kernel<<<dim3(PIX / NT, 4, B_SZ), 256, GEMM_SMEM_BYTES>>>();
    fwht_inv_kernel<<<B_SZ * C_SZ, 256>>>(x, out);
}

// round 12
// speedup vs baseline: 1.1357x; 1.1357x over previous
#include <cuda_runtime.h>
#include <cuda_fp16.h>
#include <cstdint>
#include <mma.h>

using namespace nvcuda;

// ---------------------------------------------------------------------------
// Problem constants
// ---------------------------------------------------------------------------
#define B_SZ   32
#define C_SZ   256      // C_in == C_out
#define PIX    4096     // 64*64
#define PODS   2

// scratch:  F = 2D-WHT(x) as fp16, transposed pixel order [b][c][w*64+h]
// scratch2: S = sum_p softthr(v*W@F) as fp16 (same pixel order)
__device__ __half  g_scratch [(size_t)B_SZ * C_SZ * PIX];   // 64 MiB
__device__ __half  g_scratch2[(size_t)B_SZ * C_SZ * PIX];   // 64 MiB
__device__ __half  g_Wh[(size_t)PODS * C_SZ * C_SZ];        // W in fp16
__device__ float4  g_vt[PIX];   // per scratch-pixel: (v0, T0, v1, T1)

// ---------------------------------------------------------------------------
// cp.async helpers (portable sm_80+)
// ---------------------------------------------------------------------------
__device__ __forceinline__ void cp_async16(void* smem_dst, const void* gsrc) {
    unsigned int s = (unsigned int)__cvta_generic_to_shared(smem_dst);
    asm volatile("cp.async.cg.shared.global [%0], [%1], 16;\n" :: "r"(s), "l"(gsrc));
}
#define CP_COMMIT() asm volatile("cp.async.commit_group;\n" ::: "memory")
#define CP_WAIT0()  asm volatile("cp.async.wait_group 0;\n" ::: "memory")

// ---------------------------------------------------------------------------
// FWHT-64 with 4 contiguous elements per thread: element g = 4*(lane&15)+k,
// two independent rows per warp (lanes 0-15 / 16-31). Stages: strides 1,2
// in-register; strides 4..32 via lane-xor shuffles 1,2,4,8 (stay in-group).
// ---------------------------------------------------------------------------
__device__ __forceinline__ void fwht64x4(float4& e, int L) {
    // stride 1
    float a0 = e.x + e.y, a1 = e.x - e.y;
    float a2 = e.z + e.w, a3 = e.z - e.w;
    // stride 2
    e.x = a0 + a2; e.z = a0 - a2;
    e.y = a1 + a3; e.w = a1 - a3;
    // strides 4,8,16,32 -> lane xor 1,2,4,8
#pragma unroll
    for (int st = 1; st <= 8; st <<= 1) {
        float tx = __shfl_xor_sync(0xffffffffu, e.x, st);
        float ty = __shfl_xor_sync(0xffffffffu, e.y, st);
        float tz = __shfl_xor_sync(0xffffffffu, e.z, st);
        float tw = __shfl_xor_sync(0xffffffffu, e.w, st);
        if (L & st) { e.x = tx - e.x; e.y = ty - e.y; e.z = tz - e.z; e.w = tw - e.w; }
        else        { e.x = e.x + tx; e.y = e.y + ty; e.z = e.z + tz; e.w = e.w + tw; }
    }
}

// ---------------------------------------------------------------------------
// Kernel 0: prep — permuted (v,T) LUT + W -> fp16
// ---------------------------------------------------------------------------
__global__ void prep_kernel(const float* __restrict__ v, const float* __restrict__ T,
                            const float* __restrict__ W) {
    int i = blockIdx.x * 256 + threadIdx.x;
    if (i < PIX) {
        int p = i;                                    // scratch order: w*64+h
        int vidx = ((p & 63) << 6) | (p >> 6);        // natural order: h*64+w
        g_vt[p] = make_float4(v[vidx], T[vidx], v[PIX + vidx], T[PIX + vidx]);
    }
    for (int j = i; j < PODS * C_SZ * C_SZ; j += gridDim.x * 256)
        g_Wh[j] = __float2half_rn(W[j]);
}

// ---------------------------------------------------------------------------
// Kernel 1: forward 2D WHT per (b,c) image -> g_scratch fp16 ([w][h] order)
//   row pass along w (float4 loads) -> smem transpose (scalar) -> col pass
//   along h (scalar tile reads) -> fp16 stores (8B) in [w][h] order.
// ---------------------------------------------------------------------------
__global__ void __launch_bounds__(256) fwht_fwd_kernel(const float* __restrict__ x) {
    __shared__ float tile[64 * 65];
    const int img = blockIdx.x;                 // b*256 + c
    const float* src = x + (size_t)img * PIX;
    __half* dst = g_scratch + (size_t)img * PIX;
    const int t = threadIdx.x;
    const int warp = t >> 5, lane = t & 31;
    const int L = lane & 15, half = lane >> 4;

    // row pass: along w
#pragma unroll
    for (int i = 0; i < 4; i++) {
        int h = warp * 8 + i * 2 + half;
        float4 e = *reinterpret_cast<const float4*>(src + h * 64 + 4 * L);
        fwht64x4(e, L);
        // transpose into tile[w][h] (scalar stores, pitch 65)
        tile[(4 * L + 0) * 65 + h] = e.x;
        tile[(4 * L + 1) * 65 + h] = e.y;
        tile[(4 * L + 2) * 65 + h] = e.z;
        tile[(4 * L + 3) * 65 + h] = e.w;
    }
    __syncthreads();

    // column pass: along h; scalar tile reads (pitch 65 is odd -> no LDS.128)
#pragma unroll
    for (int i = 0; i < 4; i++) {
        int w = warp * 8 + i * 2 + half;
        const float* tr = &tile[w * 65 + 4 * L];
        float4 e = make_float4(tr[0], tr[1], tr[2], tr[3]);
        fwht64x4(e, L);
        __half2 h01 = __floats2half2_rn(e.x, e.y);
        __half2 h23 = __floats2half2_rn(e.z, e.w);
        uint2 pk = make_uint2(*reinterpret_cast<unsigned int*>(&h01),
                              *reinterpret_cast<unsigned int*>(&h23));
        *reinterpret_cast<uint2*>(dst + w * 64 + 4 * L) = pk;
    }
}

// ---------------------------------------------------------------------------
// Kernel 2: fp16 wmma dual-pod GEMM + soft-threshold + pod-sum (round-9 shape)
//   Grid: (64 pixtiles, 2 M-halves, 32 b). CTA: M=128, N=64, K=256 in 4
//   chunks of 64, A double-buffered cp.async, B panel K-resident.
//   8 warps 4(M) x 2(N): warp tile 32x32 per pod. 2 CTAs/SM.
// ---------------------------------------------------------------------------
#define NT     64
#define KCH    64
#define LDBH   72                               // halves; 144B rows
#define LDAH   72                               // halves; 144B rows
#define BS_HALVES    (256 * LDBH)               // 18432 halves = 36864 B
#define A_POD_HALVES (128 * LDAH)               // 9216 halves = 18432 B
#define GEMM_SMEM_BYTES ((BS_HALVES + 4 * A_POD_HALVES) * 2)   // 110592 B

__device__ __forceinline__ float softthr(float y, float vv, float tt) {
    float z = vv * y;
    return copysignf(fmaxf(fabsf(z) - tt, 0.0f), z);
}

__global__ void __launch_bounds__(256, 2) gemm_pods_kernel() {
    extern __shared__ __half smh[];
    __half* Bs   = smh;                          // [256][72]
    __half* Abuf = smh + BS_HALVES;              // 4 x 9216: [buf][pod]

    const int pix0  = blockIdx.x * NT;
    const int mhalf = blockIdx.y;
    const int b     = blockIdx.z;
    const int t     = threadIdx.x;
    const int warp  = t >> 5, lane = t & 31;
    const int wm    = warp >> 1;                 // 0..3  (M)
    const int wn    = warp & 1;                  // 0..1  (N)

    const __half* Fb = g_scratch + (size_t)b * C_SZ * PIX;
    __half*       Ob = g_scratch2 + (size_t)b * C_SZ * PIX;
    const __half* W0 = g_Wh + (size_t)mhalf * 128 * C_SZ;
    const __half* W1 = W0 + (size_t)C_SZ * C_SZ;

    // ---- B panel: 256 (c) x 64 (pix) fp16, K-resident ----
#pragma unroll
    for (int i = 0; i < 8; i++) {
        int idx = i * 256 + t;                   // 2048 x 16B
        int r = idx >> 3, u = idx & 7;
        cp_async16(Bs + r * LDBH + u * 8, Fb + (size_t)r * PIX + pix0 + u * 8);
    }
    // ---- A chunk 0 (both pods) into buffer 0: 128 rows x 64 halves each ----
#pragma unroll
    for (int i = 0; i < 4; i++) {
        int idx = i * 256 + t;                   // 1024 x 16B per pod
        int r = idx >> 3, u = idx & 7;
        cp_async16(Abuf + r * LDAH + u * 8,                  W0 + (size_t)r * C_SZ + u * 8);
        cp_async16(Abuf + A_POD_HALVES + r * LDAH + u * 8,   W1 + (size_t)r * C_SZ + u * 8);
    }
    CP_COMMIT();

    wmma::fragment<wmma::accumulator, 16, 16, 16, float> acc0[2][2], acc1[2][2];
#pragma unroll
    for (int mi = 0; mi < 2; mi++)
#pragma unroll
        for (int ni = 0; ni < 2; ni++) {
            wmma::fill_fragment(acc0[mi][ni], 0.0f);
            wmma::fill_fragment(acc1[mi][ni], 0.0f);
        }

#pragma unroll 1
    for (int kci = 0; kci < 4; kci++) {
        CP_WAIT0();
        __syncthreads();
        if (kci < 3) {
            int kc = (kci + 1) * KCH;
            __half* A0 = Abuf + ((kci + 1) & 1) * 2 * A_POD_HALVES;
            __half* A1 = A0 + A_POD_HALVES;
#pragma unroll
            for (int i = 0; i < 4; i++) {
                int idx = i * 256 + t;
                int r = idx >> 3, u = idx & 7;
                cp_async16(A0 + r * LDAH + u * 8, W0 + (size_t)r * C_SZ + kc + u * 8);
                cp_async16(A1 + r * LDAH + u * 8, W1 + (size_t)r * C_SZ + kc + u * 8);
            }
            CP_COMMIT();
        }
        const __half* A0 = Abuf + (kci & 1) * 2 * A_POD_HALVES;
        const __half* A1 = A0 + A_POD_HALVES;
#pragma unroll
        for (int ks = 0; ks < KCH; ks += 16) {
            wmma::fragment<wmma::matrix_b, 16, 16, 16, __half, wmma::row_major> bf[2];
#pragma unroll
            for (int ni = 0; ni < 2; ni++)
                wmma::load_matrix_sync(bf[ni],
                    Bs + (kci * KCH + ks) * LDBH + wn * 32 + ni * 16, LDBH);
#pragma unroll
            for (int mi = 0; mi < 2; mi++) {
                wmma::fragment<wmma::matrix_a, 16, 16, 16, __half, wmma::row_major> af0, af1;
                wmma::load_matrix_sync(af0, A0 + (wm * 32 + mi * 16) * LDAH + ks, LDAH);
                wmma::load_matrix_sync(af1, A1 + (wm * 32 + mi * 16) * LDAH + ks, LDAH);
#pragma unroll
                for (int ni = 0; ni < 2; ni++) {
                    wmma::mma_sync(acc0[mi][ni], af0, bf[ni], acc0[mi][ni]);
                    wmma::mma_sync(acc1[mi][ni], af1, bf[ni], acc1[mi][ni]);
                }
            }
        }
    }

    // ---- epilogue: warp-private fp32 patches (32x32 per pod, stride 36) ----
    __syncthreads();
    float* patch0 = reinterpret_cast<float*>(smh) + warp * 2304;  // 2 x 32*36
    float* patch1 = patch0 + 1152;

#pragma unroll
    for (int mi = 0; mi < 2; mi++)
#pragma unroll
        for (int ni = 0; ni < 2; ni++) {
            wmma::store_matrix_sync(patch0 + mi * 16 * 36 + ni * 16, acc0[mi][ni], 36, wmma::mem_row_major);
            wmma::store_matrix_sync(patch1 + mi * 16 * 36 + ni * 16, acc1[mi][ni], 36, wmma::mem_row_major);
        }
    __syncwarp();

    {
        const int colbase = pix0 + wn * 32;
        const float4* vt = g_vt + colbase;
        const int r = lane;                           // 0..31 row within warp tile
        const int o = mhalf * 128 + wm * 32 + r;
        __half* dst = Ob + (size_t)o * PIX + colbase;
        unsigned int packed[16];
#pragma unroll
        for (int j2 = 0; j2 < 16; j2++) {
            float4 w4a = vt[j2 * 2 + 0];
            float4 w4b = vt[j2 * 2 + 1];
            float ya0 = patch0[r * 36 + j2 * 2 + 0];
            float yb0 = patch1[r * 36 + j2 * 2 + 0];
            float ya1 = patch0[r * 36 + j2 * 2 + 1];
            float yb1 = patch1[r * 36 + j2 * 2 + 1];
            float s0 = softthr(ya0, w4a.x, w4a.y) + softthr(yb0, w4a.z, w4a.w);
            float s1 = softthr(ya1, w4b.x, w4b.y) + softthr(yb1, w4b.z, w4b.w);
            __half2 h2 = __floats2half2_rn(s0, s1);
            packed[j2] = *reinterpret_cast<unsigned int*>(&h2);
        }
        uint4* d4 = reinterpret_cast<uint4*>(dst);
#pragma unroll
        for (int q = 0; q < 4; q++)
            d4[q] = make_uint4(packed[q * 4 + 0], packed[q * 4 + 1],
                               packed[q * 4 + 2], packed[q * 4 + 3]);
    }
}

// ---------------------------------------------------------------------------
// Kernel 3: inverse 2D WHT (/4096) + residual; un-transposes scratch2 (fp16).
//   pass 1 along h (8B fp16 loads) -> transpose (scalar) -> pass 2 along w
//   (scalar tile reads) -> float4 out with residual.
// ---------------------------------------------------------------------------
__global__ void __launch_bounds__(256) fwht_inv_kernel(const float* __restrict__ x,
                                                       float* __restrict__ out) {
    __shared__ float tile[64 * 65];
    const int img = blockIdx.x;
    const __half* src = g_scratch2 + (size_t)img * PIX; // [w][h] order
    const float* xr  = x + (size_t)img * PIX;           // [h][w] order
    float* dst = out + (size_t)img * PIX;               // [h][w] order
    const int t = threadIdx.x;
    const int warp = t >> 5, lane = t & 31;
    const int L = lane & 15, half = lane >> 4;

    // pass 1: along h (contiguous in scratch layout)
#pragma unroll
    for (int i = 0; i < 4; i++) {
        int w = warp * 8 + i * 2 + half;
        uint2 pk = *reinterpret_cast<const uint2*>(src + w * 64 + 4 * L);
        __half2 h01 = *reinterpret_cast<__half2*>(&pk.x);
        __half2 h23 = *reinterpret_cast<__half2*>(&pk.y);
        float2 f01 = __half22float2(h01);
        float2 f23 = __half22float2(h23);
        float4 e = make_float4(f01.x, f01.y, f23.x, f23.y);
        fwht64x4(e, L);
        // transpose into tile[h][w] (scalar stores, pitch 65)
        tile[(4 * L + 0) * 65 + w] = e.x;
        tile[(4 * L + 1) * 65 + w] = e.y;
        tile[(4 * L + 2) * 65 + w] = e.z;
        tile[(4 * L + 3) * 65 + w] = e.w;
    }
    __syncthreads();

    const float inv = 1.0f / 4096.0f;
    // pass 2: along w; scalar tile reads; finish in natural [h][w], float4 out
#pragma unroll
    for (int i = 0; i < 4; i++) {
        int h = warp * 8 + i * 2 + half;
        const float* tr = &tile[h * 65 + 4 * L];
        float4 e = make_float4(tr[0], tr[1], tr[2], tr[3]);
        fwht64x4(e, L);
        float4 xv = *reinterpret_cast<const float4*>(xr + h * 64 + 4 * L);
        float4 o;
        o.x = e.x * inv + xv.x;
        o.y = e.y * inv + xv.y;
        o.z = e.z * inv + xv.z;
        o.w = e.w * inv + xv.w;
        *reinterpret_cast<float4*>(dst + h * 64 + 4 * L) = o;
    }
}

// ---------------------------------------------------------------------------
// Launch
// ---------------------------------------------------------------------------
extern "C" void kernel_launch(void* const* d_in, const int* in_sizes, int n_in,
                              void* d_out, int out_size) {
    const float* x  = (const float*)d_in[0];   // (32, 256, 64, 64)
    const float* v  = (const float*)d_in[1];   // (2, 64, 64)
    const float* W  = (const float*)d_in[2];   // (2, 256, 256)
    const float* T  = (const float*)d_in[3];   // (2, 64, 64)
    float* out = (float*)d_out;

    static bool attr_set = false;
    if (!attr_set) {
        cudaFuncSetAttribute(gemm_pods_kernel,
                             cudaFuncAttributeMaxDynamicSharedMemorySize,
                             GEMM_SMEM_BYTES);
        attr_set = true;
    }

    prep_kernel<<<PIX / 256, 256>>>(v, T, W);
    fwht_fwd_kernel<<<B_SZ * C_SZ, 256>>>(x);
    gemm_pods_kernel<<<dim3(PIX / NT, 2, B_SZ), 256, GEMM_SMEM_BYTES>>>();
    fwht_inv_kernel<<<B_SZ * C_SZ, 256>>>(x, out);
}